// round 6
// baseline (speedup 1.0000x reference)
#include <cuda_runtime.h>
#include <cuda_fp16.h>
#include <cstdint>

// Problem constants (match reference)
#define N_USERS 200000
#define N_ITEMS 400000
#define N_NODES (N_USERS + N_ITEMS)   // 600000
#define EMB_DIM 128
#define N_EDGES 3000000
#define VEC4_PER_ROW (EMB_DIM / 4)    // 32
#define TOTAL_F ((size_t)N_NODES * EMB_DIM)   // 76.8M elems
#define TOTAL_V4 (TOTAL_F / 4)                // 19.2M

#define SCAN_BLOCK 1024
#define N_SCAN_BLOCKS ((N_NODES + SCAN_BLOCK - 1) / SCAN_BLOCK)  // 586

// Static scratch (allowed: __device__ globals; zero-init on load)
__device__ __half g_bufX[TOTAL_F];     // fp16 concat of inputs, 153.6 MB
__device__ __half g_bufA[TOTAL_F];     // 153.6 MB
__device__ __half g_bufB[TOTAL_F];     // 153.6 MB
__device__ int    g_count[N_NODES];    // zero at start of every replay (invariant)
__device__ int    g_offsetL[N_NODES + 1];  // block-local exclusive scan
__device__ int    g_pos[N_NODES];          // mutable copy for permute
__device__ int    g_bsum[SCAN_BLOCK];      // per-block sums -> exclusive scanned
__device__ int2   g_pair[N_EDGES];         // (col, val-as-int) packed

// ---------------------------------------------------------------------------
// Launch 1: histogram + (grid-stride) fp32->fp16 input conversion fused
// ---------------------------------------------------------------------------
__global__ void hist_convert_kernel(const int* __restrict__ rows,
                                    int* __restrict__ count,
                                    const float4* __restrict__ user,
                                    const float4* __restrict__ item,
                                    uint2* __restrict__ X2) {
    size_t tid = (size_t)blockIdx.x * blockDim.x + threadIdx.x;
    if (tid < N_EDGES) atomicAdd(&count[rows[tid]], 1);

    const size_t user_v4 = (size_t)N_USERS * VEC4_PER_ROW;
    size_t stride = (size_t)gridDim.x * blockDim.x;
    for (size_t i = tid; i < TOTAL_V4; i += stride) {
        float4 v = (i < user_v4) ? __ldg(user + i) : __ldg(item + i - user_v4);
        __half2 h0 = __floats2half2_rn(v.x, v.y);
        __half2 h1 = __floats2half2_rn(v.z, v.w);
        uint2 raw;
        raw.x = *reinterpret_cast<unsigned*>(&h0);
        raw.y = *reinterpret_cast<unsigned*>(&h1);
        X2[i] = raw;
    }
}

// ---------------------------------------------------------------------------
// Launch 2: block-local exclusive scan of count; emits block sums.
// Also zeroes count (restores the replay invariant) and seeds pos.
// ---------------------------------------------------------------------------
__global__ void scan1_kernel(int* __restrict__ count,
                             int* __restrict__ offsetL,
                             int* __restrict__ pos,
                             int* __restrict__ bsum) {
    __shared__ int sh[SCAN_BLOCK];
    int i = blockIdx.x * SCAN_BLOCK + threadIdx.x;
    int v = (i < N_NODES) ? count[i] : 0;
    if (i < N_NODES) count[i] = 0;   // restore invariant for next replay
    sh[threadIdx.x] = v;
    __syncthreads();
    #pragma unroll
    for (int d = 1; d < SCAN_BLOCK; d <<= 1) {
        int t = (threadIdx.x >= d) ? sh[threadIdx.x - d] : 0;
        __syncthreads();
        sh[threadIdx.x] += t;
        __syncthreads();
    }
    if (i < N_NODES) {
        int excl = sh[threadIdx.x] - v;
        offsetL[i] = excl;
        pos[i] = excl;
    }
    if (threadIdx.x == SCAN_BLOCK - 1) bsum[blockIdx.x] = sh[SCAN_BLOCK - 1];
}

// ---------------------------------------------------------------------------
// Launch 3: exclusive scan of block sums (single block)
// ---------------------------------------------------------------------------
__global__ void scan2_kernel(int* __restrict__ bsum, int nb) {
    __shared__ int sh[SCAN_BLOCK];
    int v = (threadIdx.x < nb) ? bsum[threadIdx.x] : 0;
    sh[threadIdx.x] = v;
    __syncthreads();
    #pragma unroll
    for (int d = 1; d < SCAN_BLOCK; d <<= 1) {
        int t = (threadIdx.x >= d) ? sh[threadIdx.x - d] : 0;
        __syncthreads();
        sh[threadIdx.x] += t;
        __syncthreads();
    }
    if (threadIdx.x < nb) bsum[threadIdx.x] = sh[threadIdx.x] - v;  // exclusive
}

// ---------------------------------------------------------------------------
// Launch 4: permute edges into CSR order (global offset = local + bsum)
// ---------------------------------------------------------------------------
__global__ void permute_kernel(const int* __restrict__ rows,
                               const int* __restrict__ cols,
                               const float* __restrict__ vals,
                               int* __restrict__ pos,
                               const int* __restrict__ bsum,
                               int2* __restrict__ pair) {
    int e = blockIdx.x * blockDim.x + threadIdx.x;
    if (e >= N_EDGES) return;
    int r = rows[e];
    int p = atomicAdd(&pos[r], 1) + __ldg(&bsum[r >> 10]);
    int2 pr;
    pr.x = cols[e];
    pr.y = __float_as_int(vals[e]);
    pair[p] = pr;
}

// ---------------------------------------------------------------------------
// fp16 row helpers (8B per lane)
// ---------------------------------------------------------------------------
__device__ __forceinline__ float4 load_h4(const __half* row, int lane) {
    uint2 raw = __ldg(reinterpret_cast<const uint2*>(row) + lane);
    __half2 h0 = *reinterpret_cast<__half2*>(&raw.x);
    __half2 h1 = *reinterpret_cast<__half2*>(&raw.y);
    float2 f0 = __half22float2(h0);
    float2 f1 = __half22float2(h1);
    return make_float4(f0.x, f0.y, f1.x, f1.y);
}

__device__ __forceinline__ void store_h4(__half* row, int lane, float4 v) {
    __half2 h0 = __floats2half2_rn(v.x, v.y);
    __half2 h1 = __floats2half2_rn(v.z, v.w);
    uint2 raw;
    raw.x = *reinterpret_cast<unsigned*>(&h0);
    raw.y = *reinterpret_cast<unsigned*>(&h1);
    *(reinterpret_cast<uint2*>(row) + lane) = raw;
}

// ---------------------------------------------------------------------------
// Launches 5-7: pull SpMM, warp-per-row, fp16 gather, fp32 accumulate.
// FUSED (layer 3): out = 0.25*(x0_fp32 + A + B + y)
// ---------------------------------------------------------------------------
template <bool FUSED>
__global__ void __launch_bounds__(512)
spmm_kernel(const int* __restrict__ offsetL,
            const int* __restrict__ bsum,
            const int2* __restrict__ pair,
            const __half* __restrict__ xH,    // gather src (fp16)
            __half* __restrict__ dstH,        // layer output (fp16)
            const float4* __restrict__ u,     // FUSED: user embs fp32
            const float4* __restrict__ it,    // FUSED: item embs fp32
            const __half* __restrict__ accA,  // FUSED: layer-1 out
            const __half* __restrict__ accB,  // FUSED: layer-2 out
            float4* __restrict__ out) {       // FUSED: final out fp32
    int lane = threadIdx.x & 31;
    int r = (blockIdx.x * blockDim.x + threadIdx.x) >> 5;
    if (r >= N_NODES) return;

    int j = __ldg(offsetL + r) + __ldg(bsum + (r >> 10));
    int end = (r == N_NODES - 1)
                  ? N_EDGES
                  : __ldg(offsetL + r + 1) + __ldg(bsum + ((r + 1) >> 10));

    float4 acc0 = make_float4(0.f, 0.f, 0.f, 0.f);
    float4 acc1 = make_float4(0.f, 0.f, 0.f, 0.f);

    #pragma unroll 1
    for (; j + 2 <= end; j += 2) {
        int2 e0 = __ldg(pair + j);
        int2 e1 = __ldg(pair + j + 1);
        float4 m0 = load_h4(xH + (size_t)e0.x * EMB_DIM, lane);
        float4 m1 = load_h4(xH + (size_t)e1.x * EMB_DIM, lane);
        float v0 = __int_as_float(e0.y);
        float v1 = __int_as_float(e1.y);
        acc0.x += v0 * m0.x; acc0.y += v0 * m0.y;
        acc0.z += v0 * m0.z; acc0.w += v0 * m0.w;
        acc1.x += v1 * m1.x; acc1.y += v1 * m1.y;
        acc1.z += v1 * m1.z; acc1.w += v1 * m1.w;
    }
    if (j < end) {
        int2 e0 = __ldg(pair + j);
        float4 m0 = load_h4(xH + (size_t)e0.x * EMB_DIM, lane);
        float v0 = __int_as_float(e0.y);
        acc0.x += v0 * m0.x; acc0.y += v0 * m0.y;
        acc0.z += v0 * m0.z; acc0.w += v0 * m0.w;
    }

    float4 acc;
    acc.x = acc0.x + acc1.x; acc.y = acc0.y + acc1.y;
    acc.z = acc0.z + acc1.z; acc.w = acc0.w + acc1.w;

    if (FUSED) {
        size_t idx = (size_t)r * VEC4_PER_ROW + lane;
        float4 x0 = (r < N_USERS)
                        ? __ldg(u + (size_t)r * VEC4_PER_ROW + lane)
                        : __ldg(it + (size_t)(r - N_USERS) * VEC4_PER_ROW + lane);
        float4 a = load_h4(accA + (size_t)r * EMB_DIM, lane);
        float4 b = load_h4(accB + (size_t)r * EMB_DIM, lane);
        float4 o;
        o.x = 0.25f * (x0.x + a.x + b.x + acc.x);
        o.y = 0.25f * (x0.y + a.y + b.y + acc.y);
        o.z = 0.25f * (x0.z + a.z + b.z + acc.z);
        o.w = 0.25f * (x0.w + a.w + b.w + acc.w);
        out[idx] = o;
    } else {
        store_h4(dstH + (size_t)r * EMB_DIM, lane, acc);
    }
}

extern "C" void kernel_launch(void* const* d_in, const int* in_sizes, int n_in,
                              void* d_out, int out_size) {
    const float4* emb_user = (const float4*)d_in[0];
    const float4* emb_item = (const float4*)d_in[1];
    const int* edge_row = (const int*)d_in[2];
    const int* edge_col = (const int*)d_in[3];
    const float* edge_val = (const float*)d_in[4];
    float4* out = (float4*)d_out;

    __half *X, *A, *B;
    int *count_, *offsetL_, *pos_, *bsum_;
    int2 *pair_;
    cudaGetSymbolAddress((void**)&X, g_bufX);
    cudaGetSymbolAddress((void**)&A, g_bufA);
    cudaGetSymbolAddress((void**)&B, g_bufB);
    cudaGetSymbolAddress((void**)&count_, g_count);
    cudaGetSymbolAddress((void**)&offsetL_, g_offsetL);
    cudaGetSymbolAddress((void**)&pos_, g_pos);
    cudaGetSymbolAddress((void**)&bsum_, g_bsum);
    cudaGetSymbolAddress((void**)&pair_, g_pair);

    const int T = 256;
    const int gridEdge = (N_EDGES + T - 1) / T;
    const int TS = 512;
    const int gridRow = (int)(((size_t)N_NODES * 32 + TS - 1) / TS);

    // 1: histogram + fp16 conversion (count starts zero: first run by
    //    zero-init, later replays restored by scan1)
    hist_convert_kernel<<<gridEdge, T>>>(edge_row, count_,
                                         emb_user, emb_item, (uint2*)X);
    // 2: local scan (+ zero count, seed pos)
    scan1_kernel<<<N_SCAN_BLOCKS, SCAN_BLOCK>>>(count_, offsetL_, pos_, bsum_);
    // 3: block-sum exclusive scan
    scan2_kernel<<<1, SCAN_BLOCK>>>(bsum_, N_SCAN_BLOCKS);
    // 4: permute edges into CSR order
    permute_kernel<<<gridEdge, T>>>(edge_row, edge_col, edge_val,
                                    pos_, bsum_, pair_);

    // 5: Layer 1: gather X -> A
    spmm_kernel<false><<<gridRow, TS>>>(offsetL_, bsum_, pair_, X, A,
                                        nullptr, nullptr, nullptr, nullptr,
                                        nullptr);
    // 6: Layer 2: gather A -> B
    spmm_kernel<false><<<gridRow, TS>>>(offsetL_, bsum_, pair_, A, B,
                                        nullptr, nullptr, nullptr, nullptr,
                                        nullptr);
    // 7: Layer 3 fused: gather B, out = 0.25*(x0 + A + B + y)
    spmm_kernel<true><<<gridRow, TS>>>(offsetL_, bsum_, pair_, B, nullptr,
                                       emb_user, emb_item, A, B, out);
}